// round 10
// baseline (speedup 1.0000x reference)
#include <cuda_runtime.h>
#include <math.h>

#define EPSV 1e-5f
#define VFLOOR 1e-6f

// Fixed shape: B=4, L=4096, D=2048, G=16 (gs=128). Chunk = 8 rows.
constexpr int Lc   = 4096;
constexpr int Gc   = 16;
constexpr int Dc   = 2048;
constexpr int CH   = 8;
constexpr int NCH  = Lc / CH;     // 512 chunks per batch
constexpr int SUP  = 32;          // chunks per superchunk
constexpr int NSUP = NCH / SUP;   // 16
constexpr int MAXB = 8;

// per-chunk aggregates + arrival counters
__device__ float d_S    [MAXB * Gc * NCH];
__device__ float d_Q    [MAXB * Gc * NCH];
__device__ float d_C    [MAXB * NCH];
__device__ int   d_cflag[MAXB * NCH];          // target Gc (16 warps)
// per-superchunk accumulators + arrival counters
__device__ float d_sS   [MAXB * Gc * NSUP];
__device__ float d_sQ   [MAXB * Gc * NSUP];
__device__ float d_sC   [MAXB * NSUP];
__device__ int   d_scnt [MAXB * NSUP];         // target SUP*Gc (512)

__global__ void k_init(int nc, int nsg, int ns) {
    const int i = blockIdx.x * blockDim.x + threadIdx.x;
    if (i < nc)  d_cflag[i] = 0;
    if (i < nsg) { d_sS[i] = 0.f; d_sQ[i] = 0.f; }
    if (i < ns)  { d_sC[i] = 0.f; d_scnt[i] = 0; }
}

__device__ __forceinline__ int ld_acq(const int* p) {
    int v;
    asm volatile("ld.acquire.gpu.global.b32 %0, [%1];" : "=r"(v) : "l"(p));
    return v;
}
__device__ __forceinline__ void red_rel_add(int* p, int v) {
    asm volatile("red.release.gpu.global.add.s32 [%0], %1;" :: "l"(p), "r"(v) : "memory");
}

// ---------------------------------------------------------------------------
// Fused single-pass kernel. Block = one 8-row chunk; warp g owns group g.
// Phase A: reduce + publish (chunk record + superchunk atomic accumulate).
// Phase B: O(1) hierarchical lookback (<=15 supers + <=31 chunks, lane-par).
// Phase C: re-read x (L2-hot), normalize, streaming-store y.
// ---------------------------------------------------------------------------
__global__ void __launch_bounds__(512, 3)
k_fused(const float* __restrict__ x,
        const int*   __restrict__ pcnt,
        const float* __restrict__ pmean,
        const float* __restrict__ pvar,
        const int*   __restrict__ pmask,
        const float* __restrict__ wgt,
        const float* __restrict__ bias,
        float*       __restrict__ outF,
        int B, int writeTail, long long tailOff)
{
    const unsigned FULL = 0xffffffffu;
    const int tid  = threadIdx.x;
    const int b    = blockIdx.x >> 9;        // / NCH
    const int ch   = blockIdx.x & (NCH - 1);
    const int lane = tid & 31;
    const int g    = tid >> 5;
    const int rowBase = b * Lc + ch * CH;

    // ---- Phase A: 8 row-sums, packed 9-shuffle reduce ---------------------
    const float4* xr = (const float4*)x;
    float s[CH];
    #pragma unroll
    for (int r = 0; r < CH; r++) {
        const float4 t = xr[(size_t)(rowBase + r) * (Dc / 4) + g * 32 + lane];
        s[r] = (t.x + t.y) + (t.z + t.w);
    }
    // 8 -> 4 (xor 1): lane bit0 selects row parity
    float a4[4];
    #pragma unroll
    for (int i = 0; i < 4; i++) {
        const float keep = (lane & 1) ? s[2*i+1] : s[2*i];
        const float send = (lane & 1) ? s[2*i]   : s[2*i+1];
        a4[i] = keep + __shfl_xor_sync(FULL, send, 1);
    }
    // 4 -> 2 (xor 2)
    float a2[2];
    #pragma unroll
    for (int i = 0; i < 2; i++) {
        const float keep = (lane & 2) ? a4[2*i+1] : a4[2*i];
        const float send = (lane & 2) ? a4[2*i]   : a4[2*i+1];
        a2[i] = keep + __shfl_xor_sync(FULL, send, 2);
    }
    // 2 -> 1 (xor 4)
    float acc;
    {
        const float keep = (lane & 4) ? a2[1] : a2[0];
        const float send = (lane & 4) ? a2[0] : a2[1];
        acc = keep + __shfl_xor_sync(FULL, send, 4);
    }
    // finish across octets
    acc += __shfl_xor_sync(FULL, acc, 8);
    acc += __shfl_xor_sync(FULL, acc, 16);
    const float mygm = acc * (1.0f / 128.0f);       // row (lane&7) group mean
    const float myv  = pmask[rowBase + (lane & 7)] ? 1.0f : 0.0f;

    // in-chunk inclusive scan over rows (lanes 0..7 meaningful)
    float sS = mygm * myv;
    float sQ = mygm * mygm * myv;
    float sC = myv;
    #pragma unroll
    for (int o = 1; o < CH; o <<= 1) {
        const float b0 = __shfl_up_sync(FULL, sS, o);
        const float b1 = __shfl_up_sync(FULL, sQ, o);
        const float b2 = __shfl_up_sync(FULL, sC, o);
        if (lane >= o) { sS += b0; sQ += b1; sC += b2; }
    }

    // publish chunk totals (lane 7 = inclusive total) + superchunk atomics
    const int mysup = ch >> 5;                    // / SUP
    if (lane == CH - 1) {
        const int cidx = (b * Gc + g) * NCH + ch;
        const int sgid = (b * Gc + g) * NSUP + mysup;
        d_S[cidx] = sS;
        d_Q[cidx] = sQ;
        atomicAdd(&d_sS[sgid], sS);
        atomicAdd(&d_sQ[sgid], sQ);
        if (g == 0) {
            d_C[b * NCH + ch] = sC;
            atomicAdd(&d_sC[b * NSUP + mysup], sC);
        }
        red_rel_add(&d_cflag[b * NCH + ch], 1);           // data -> flag
        red_rel_add(&d_scnt[b * NSUP + mysup], 1);        // atomics -> cnt
    }

    // prior-state loads (overlap with lookback)
    const float pc     = (float)pcnt[b];
    const float pmeanv = pmean[b * Gc + g];
    const float pvarv  = pvar [b * Gc + g];
    float4 wv = ((const float4*)wgt)[g * 32 + lane];
    float4 bv = ((const float4*)bias)[g * 32 + lane];
    wv.x += 1.f; wv.y += 1.f; wv.z += 1.f; wv.w += 1.f;

    // ---- Phase B: hierarchical lookback (O(1) rounds) ---------------------
    float prefS = 0.f, prefQ = 0.f, prefC = 0.f;
    // complete predecessor superchunks: lane = super index < mysup
    if (lane < mysup) {
        const int sidx = b * NSUP + lane;
        while (ld_acq(&d_scnt[sidx]) < SUP * Gc) __nanosleep(30);
        prefS = d_sS[(b * Gc + g) * NSUP + lane];
        prefQ = d_sQ[(b * Gc + g) * NSUP + lane];
        prefC = d_sC[sidx];
    }
    // same-super predecessor chunks: j = supBase + lane < ch
    {
        const int j = (ch & ~(SUP - 1)) + lane;
        if (j < ch) {
            while (ld_acq(&d_cflag[b * NCH + j]) < Gc) __nanosleep(30);
            prefS += d_S[(b * Gc + g) * NCH + j];
            prefQ += d_Q[(b * Gc + g) * NCH + j];
            prefC += d_C[b * NCH + j];
        }
    }
    #pragma unroll
    for (int o = 16; o > 0; o >>= 1) {
        prefS += __shfl_xor_sync(FULL, prefS, o);
        prefQ += __shfl_xor_sync(FULL, prefQ, o);
        prefC += __shfl_xor_sync(FULL, prefC, o);
    }

    // ---- Chan closed-form streaming stats (validated R7) ------------------
    const float psum = pmeanv * pc;
    const float pm2  = pvarv * fmaxf(pc, 1.0f);
    const float S_t  = prefS + sS;
    const float Q_t  = prefQ + sQ;
    const float c_t  = prefC + sC;
    const float count_t = pc + c_t;

    float mean_t = pmeanv, var = pvarv;
    if (count_t > 0.0f) {
        mean_t = (psum + S_t) / fmaxf(count_t, 1.0f);
        float sumdd = 0.0f;
        if (c_t > 0.0f) {
            const float bm  = S_t / c_t;
            const float m2b = Q_t - bm * S_t;
            const float dlt = bm - pmeanv;
            sumdd = m2b + dlt * dlt * (pc * c_t / (pc + c_t));
        }
        var = (pm2 + sumdd) / fmaxf(count_t, 1.0f);
    }
    var = fmaxf(var, VFLOOR);
    const float myrstd = rsqrtf(var + EPSV);

    if (writeTail && ch == NCH - 1 && lane == CH - 1) {
        outF[tailOff + B + b * Gc + g]                  = mean_t;
        outF[tailOff + B + (size_t)B * Gc + b * Gc + g] = var;
        if (g == 0) outF[tailOff + b] = count_t;   // new_count
    }

    // ---- Phase C: re-read x (L2-hot), normalize, streaming-store y --------
    float mn[CH], rs[CH];
    #pragma unroll
    for (int r = 0; r < CH; r++) {
        mn[r] = __shfl_sync(FULL, mean_t, r);
        rs[r] = __shfl_sync(FULL, myrstd, r);
    }
    float4* yr = (float4*)outF;
    #pragma unroll
    for (int r = 0; r < CH; r++) {
        const size_t idx = (size_t)(rowBase + r) * (Dc / 4) + g * 32 + lane;
        const float4 t = xr[idx];
        float4 o;
        o.x = (t.x - mn[r]) * rs[r] * wv.x + bv.x;
        o.y = (t.y - mn[r]) * rs[r] * wv.y + bv.y;
        o.z = (t.z - mn[r]) * rs[r] * wv.z + bv.z;
        o.w = (t.w - mn[r]) * rs[r] * wv.w + bv.w;
        __stcs(&yr[idx], o);
    }
}

// ---------------------------------------------------------------------------
extern "C" void kernel_launch(void* const* d_in, const int* in_sizes, int n_in,
                              void* d_out, int out_size)
{
    const float* x     = (const float*)d_in[0];
    const int*   pcnt  = (const int*)d_in[1];
    const float* pmean = (const float*)d_in[2];
    const float* pvar  = (const float*)d_in[3];
    const int*   pmask = (const int*)d_in[4];
    const float* wgt   = (const float*)d_in[5];
    const float* bias  = (const float*)d_in[6];
    float*       outF  = (float*)d_out;

    const int B = in_sizes[1];
    const int G = in_sizes[2] / B;     // 16
    const int D = in_sizes[5];         // 2048
    const int L = in_sizes[4] / B;     // 4096
    (void)G; (void)D; (void)L;

    const long long BLD = (long long)B * L * D;
    const long long expected = BLD + B + 2LL * B * G;
    const int writeTail = (out_size >= expected) ? 1 : 0;

    const int nc  = B * NCH;
    const int nsg = B * Gc * NSUP;
    const int ns  = B * NSUP;
    const int nmax = nc > nsg ? nc : nsg;
    k_init <<<(nmax + 511) / 512, 512>>>(nc, nsg, ns);
    k_fused<<<B * NCH, 512>>>(x, pcnt, pmean, pvar, pmask, wgt, bias,
                              outF, B, writeTail, BLD);
}

// round 11
// speedup vs baseline: 2.7837x; 2.7837x over previous
#include <cuda_runtime.h>
#include <math.h>

#define EPSV 1e-5f
#define VFLOOR 1e-6f

// Fixed shape: B=4, L=4096, D=2048, G=16 (gs=128).
constexpr int Lc  = 4096;
constexpr int Gc  = 16;
constexpr int Dc  = 2048;
constexpr int CH  = 8;
constexpr int NCH = Lc / CH;      // 512
constexpr int MAXB = 8;

__device__ float  g_gmT [MAXB * Gc * Lc];   // (b,g,l) group means
__device__ float2 g_stat[MAXB * Gc * Lc];   // (b,g,l) {mean, rstd}

// ---------------------------------------------------------------------------
// K1: group means only. Block = 8-row chunk; warp g reduces group g per row.
// Default (allocating) loads so x lands in L2 for K3's reversed re-read.
// ---------------------------------------------------------------------------
__global__ void __launch_bounds__(512)
k_gm(const float* __restrict__ x)
{
    const unsigned FULL = 0xffffffffu;
    const int b    = blockIdx.x >> 9;
    const int ch   = blockIdx.x & (NCH - 1);
    const int lane = threadIdx.x & 31;
    const int g    = threadIdx.x >> 5;
    const int rowBase = b * Lc + ch * CH;

    const float4* xr = (const float4*)x;
    float4 v[CH];
    #pragma unroll
    for (int r = 0; r < CH; r++)
        v[r] = xr[(size_t)(rowBase + r) * (Dc / 4) + g * 32 + lane];

    float mygm = 0.0f;
    #pragma unroll
    for (int r = 0; r < CH; r++) {
        float s = (v[r].x + v[r].y) + (v[r].z + v[r].w);
        #pragma unroll
        for (int o = 16; o > 0; o >>= 1)
            s += __shfl_xor_sync(FULL, s, o);
        if (lane == r) mygm = s * (1.0f / 128.0f);
    }
    if (lane < CH)
        g_gmT[(b * Gc + g) * Lc + ch * CH + lane] = mygm;
}

// ---------------------------------------------------------------------------
// K2: per-(b,g) sequential-Welford scan over L (proven math).
// 64 blocks, 512 threads, 8 elems/thread. Emits (mean,rstd) float2 + tail.
// ---------------------------------------------------------------------------
__global__ void __launch_bounds__(512)
k_scan(const int* __restrict__ prev_count,
       const float* __restrict__ prev_mean,
       const float* __restrict__ prev_var,
       const int* __restrict__ pmask,
       float* __restrict__ outF,
       int B, int writeTail, long long tailOff)
{
    constexpr int P = 8;
    const int b = blockIdx.x / Gc;
    const int g = blockIdx.x - b * Gc;
    const int tid  = threadIdx.x;
    const int lane = tid & 31;
    const int wid  = tid >> 5;
    const unsigned FULL = 0xffffffffu;

    const float pc    = (float)prev_count[b];
    const float pmean = prev_mean[b * Gc + g];
    const float pvar  = prev_var[b * Gc + g];
    const float psum  = pmean * pc;
    const float pm2   = pvar * fmaxf(pc, 1.0f);

    __shared__ float smS[16], smC[16];

    const float* gmrow = &g_gmT[(b * Gc + g) * Lc];

    float gv[P], vv[P], ls[P], lc[P];
    float sa = 0.f, ca = 0.f;
    #pragma unroll
    for (int j = 0; j < P; j++) {
        const int l = tid * P + j;
        const float gmv = gmrow[l];
        const float vd  = pmask[b * Lc + l] ? 1.0f : 0.0f;
        gv[j] = gmv; vv[j] = vd;
        sa += gmv * vd;  ca += vd;
        ls[j] = sa;      lc[j] = ca;
    }

    float ws = sa, wc = ca;
    #pragma unroll
    for (int o = 1; o < 32; o <<= 1) {
        const float ns = __shfl_up_sync(FULL, ws, o);
        const float nc = __shfl_up_sync(FULL, wc, o);
        if (lane >= o) { ws += ns; wc += nc; }
    }
    const float exs = ws - sa, exc = wc - ca;

    if (lane == 31) { smS[wid] = ws; smC[wid] = wc; }
    __syncthreads();
    if (tid == 0) {
        float rs = 0.f, rc = 0.f;
        #pragma unroll
        for (int i = 0; i < 16; i++) {
            const float ts = smS[i], tc = smC[i];
            smS[i] = rs; smC[i] = rc;
            rs += ts; rc += tc;
        }
    }
    __syncthreads();
    const float baseS = smS[wid] + exs;
    const float baseC = smC[wid] + exc;

    float ddv[P], meanv[P], countv[P];
    #pragma unroll
    for (int j = 0; j < P; j++) {
        const float S = baseS + ls[j];
        const float C = baseC + lc[j];
        const float count_t = pc + C;
        const float mean_t  = (count_t > 0.f) ? (psum + S) / fmaxf(count_t, 1.f) : pmean;
        const float exS2 = S - gv[j] * vv[j];
        const float exC2 = C - vv[j];
        const float cp = pc + exC2;
        const float mean_p = (cp > 0.f) ? (psum + exS2) / fmaxf(cp, 1.f) : pmean;
        ddv[j]   = (gv[j] - mean_p) * (gv[j] - mean_t) * vv[j];
        meanv[j] = mean_t;
        countv[j] = count_t;
    }
    __syncthreads();

    float ld[P];
    float da = 0.f;
    #pragma unroll
    for (int j = 0; j < P; j++) { da += ddv[j]; ld[j] = da; }
    float wd = da;
    #pragma unroll
    for (int o = 1; o < 32; o <<= 1) {
        const float nd = __shfl_up_sync(FULL, wd, o);
        if (lane >= o) wd += nd;
    }
    const float exd = wd - da;
    if (lane == 31) smS[wid] = wd;
    __syncthreads();
    if (tid == 0) {
        float rd = 0.f;
        #pragma unroll
        for (int i = 0; i < 16; i++) { const float td = smS[i]; smS[i] = rd; rd += td; }
    }
    __syncthreads();
    const float baseD = smS[wid] + exd;

    float2* statrow = &g_stat[(size_t)(b * Gc + g) * Lc];
    #pragma unroll
    for (int j = 0; j < P; j++) {
        const int l = tid * P + j;
        const float m2 = pm2 + baseD + ld[j];
        float var = (countv[j] > 0.f) ? m2 / fmaxf(countv[j], 1.f) : pvar;
        var = fmaxf(var, VFLOOR);
        statrow[l] = make_float2(meanv[j], rsqrtf(var + EPSV));
        if (writeTail && l == Lc - 1) {
            outF[tailOff + B + b * Gc + g]                  = meanv[j];
            outF[tailOff + B + (size_t)B * Gc + b * Gc + g] = var;
            if (g == 0) outF[tailOff + b] = countv[j];
        }
    }
}

// ---------------------------------------------------------------------------
// K3: pure elementwise normalize, REVERSED block order so the first wave
// reads the tail of x (still L2-resident from K1). x read evict-first
// (__ldcs), y written evict-first (__stcs) to protect un-read x in L2.
// ---------------------------------------------------------------------------
__global__ void __launch_bounds__(512)
k_norm(const float* __restrict__ x,
       const float* __restrict__ wgt,
       const float* __restrict__ bias,
       float* __restrict__ outF)
{
    constexpr int NV = 4;
    const int tid = threadIdx.x;
    const int rbid = gridDim.x - 1 - blockIdx.x;          // reversed order
    const long long idx0 = (long long)rbid * (512 * NV) + tid;

    const int d4 = (int)(idx0 & 511);            // invariant across k (stride 512)
    float4 wv = ((const float4*)wgt)[d4];
    float4 bv = ((const float4*)bias)[d4];
    wv.x += 1.f; wv.y += 1.f; wv.z += 1.f; wv.w += 1.f;

    const float4* xr = (const float4*)x;
    float4* yr = (float4*)outF;

    float4 v[NV];
    float2 st[NV];
    #pragma unroll
    for (int k = 0; k < NV; k++) {
        const long long idx = idx0 + (long long)k * 512;
        v[k] = __ldcs(&xr[idx]);
        const int row = (int)(idx >> 9);         // b*Lc + l
        const int g   = ((int)idx >> 5) & 15;
        const int b   = row >> 12;
        const int l   = row & (Lc - 1);
        st[k] = g_stat[((size_t)(b * Gc + g)) * Lc + l];
    }
    #pragma unroll
    for (int k = 0; k < NV; k++) {
        const long long idx = idx0 + (long long)k * 512;
        const float mn = st[k].x, rs = st[k].y;
        float4 o;
        o.x = (v[k].x - mn) * rs * wv.x + bv.x;
        o.y = (v[k].y - mn) * rs * wv.y + bv.y;
        o.z = (v[k].z - mn) * rs * wv.z + bv.z;
        o.w = (v[k].w - mn) * rs * wv.w + bv.w;
        __stcs(&yr[idx], o);
    }
}

// ---------------------------------------------------------------------------
extern "C" void kernel_launch(void* const* d_in, const int* in_sizes, int n_in,
                              void* d_out, int out_size)
{
    const float* x     = (const float*)d_in[0];
    const int*   pcnt  = (const int*)d_in[1];
    const float* pmean = (const float*)d_in[2];
    const float* pvar  = (const float*)d_in[3];
    const int*   pmask = (const int*)d_in[4];
    const float* wgt   = (const float*)d_in[5];
    const float* bias  = (const float*)d_in[6];
    float*       outF  = (float*)d_out;

    const int B = in_sizes[1];
    const int G = in_sizes[2] / B;     // 16
    const int D = in_sizes[5];         // 2048
    const int L = in_sizes[4] / B;     // 4096
    (void)G; (void)D; (void)L;

    const long long BLD = (long long)B * L * D;
    const long long expected = BLD + B + 2LL * B * G;
    const int writeTail = (out_size >= expected) ? 1 : 0;

    k_gm  <<<B * NCH, 512>>>(x);
    k_scan<<<B * Gc, 512>>>(pcnt, pmean, pvar, pmask, outF, B, writeTail, BLD);

    const long long n4 = BLD / 4;                 // 8M float4
    const int blocks = (int)(n4 / (512 * 4));     // 4096
    k_norm<<<blocks, 512>>>(x, wgt, bias, outF);
}